// round 6
// baseline (speedup 1.0000x reference)
#include <cuda_runtime.h>

// Problem constants (fixed by the reference setup)
#define BB   2
#define CH   64
#define NH   8
#define DH   8
#define HW   48
#define LL   2304            // HW*HW
#define BCHL (BB*CH*LL)      // 294912
#define SEGS 9
#define QSEG 256             // LL/SEGS
#define KSEG 256

#define LOG2E 1.4426950408889634f

// Packed f32x2 helpers (sm_103a FFMA2 path)
#define FMA2(d,a,b,c) asm("fma.rn.f32x2 %0,%1,%2,%3;" : "=l"(d) : "l"(a), "l"(b), "l"(c))
#define MUL2(d,a,b)   asm("mul.rn.f32x2 %0,%1,%2;"    : "=l"(d) : "l"(a), "l"(b))
#define ADD2(d,a,b)   asm("add.rn.f32x2 %0,%1,%2;"    : "=l"(d) : "l"(a), "l"(b))
#define PACK2(d,x,y)  asm("mov.b64 %0,{%1,%2};"        : "=l"(d) : "f"(x), "f"(y))
#define UNPACK2(x,y,d) asm("mov.b64 {%0,%1},%2;"       : "=f"(x), "=f"(y) : "l"(d))
#define EX2F(r,x)     asm("ex2.approx.ftz.f32 %0,%1;"  : "=f"(r) : "f"(x))

typedef unsigned long long u64;

// Scratch (device globals — no allocation allowed)
__device__ float g_q [BCHL];          // q * d^-0.5 * log2(e)  (for EX2)
__device__ float g_k [BCHL];
__device__ float g_v [BCHL];
__device__ float g_o [BCHL];
__device__ float g_Z [SEGS][BB*NH][LL];
__device__ float g_op[SEGS][BCHL];

// ---------------------------------------------------------------------------
// K1: fused q/k/v 1x1 convs.  grid = 288 blocks x 256 thr.
// ---------------------------------------------------------------------------
__global__ __launch_bounds__(256) void k_qkv(
    const float* __restrict__ x,
    const float* __restrict__ Wq, const float* __restrict__ bq,
    const float* __restrict__ Wk, const float* __restrict__ bk,
    const float* __restrict__ Wv, const float* __restrict__ bv,
    float* __restrict__ q_out)
{
    __shared__ __align__(16) float sW[3][64*64];
    __shared__ float sb[3][64];
    const int tid = threadIdx.x;
    for (int i = tid; i < 4096; i += 256) {
        sW[0][i] = Wq[i]; sW[1][i] = Wk[i]; sW[2][i] = Wv[i];
    }
    if (tid < 64) { sb[0][tid] = bq[tid]; sb[1][tid] = bk[tid]; sb[2][tid] = bv[tid]; }
    __syncthreads();

    const int col = blockIdx.x * 16 + (tid & 15);     // 0..4607
    const int og  = tid >> 4;                          // 0..15
    const int b   = col / LL;
    const int l   = col - b * LL;

    const float* xp = x + (size_t)b * CH * LL + l;
    float xr[64];
#pragma unroll
    for (int c = 0; c < 64; c++) xr[c] = xp[c * LL];

    const float qscale = 0.35355339059327373f;  // 8^-0.5

#pragma unroll
    for (int m = 0; m < 3; m++) {
        float* dst = (m == 0) ? g_q : (m == 1) ? g_k : g_v;
#pragma unroll
        for (int j = 0; j < 4; j++) {
            const int o = og * 4 + j;
            const float4* wr = (const float4*)&sW[m][o * 64];
            float a0 = 0.f, a1 = 0.f, a2 = 0.f, a3 = 0.f;
#pragma unroll
            for (int c4 = 0; c4 < 16; c4++) {
                float4 w = wr[c4];
                a0 = fmaf(w.x, xr[c4*4+0], a0);
                a1 = fmaf(w.y, xr[c4*4+1], a1);
                a2 = fmaf(w.z, xr[c4*4+2], a2);
                a3 = fmaf(w.w, xr[c4*4+3], a3);
            }
            float r = (a0 + a1) + (a2 + a3) + sb[m][o];
            const size_t idx = ((size_t)b * CH + o) * LL + l;
            if (m == 0) {
                float rq = r * qscale;
                q_out[idx] = rq;                 // reference returns the SCALED q
                dst[idx]   = rq * LOG2E;         // internal: prescaled for EX2
            } else {
                dst[idx] = r;
            }
        }
    }
}

// ---------------------------------------------------------------------------
// K2 (pass A): partial Z over a q-segment.  Each thread owns 2 k columns
// (ONE packed pair) — low registers, high occupancy.
// grid = (bh=16, ktile=4, seg=9) x 288 thr = 576 blocks.
// ---------------------------------------------------------------------------
__global__ __launch_bounds__(288) void k_passA()
{
    const int bh = blockIdx.x;
    const int b = bh >> 3, h = bh & 7;
    const int tid = threadIdx.x;
    const int k0 = blockIdx.y * 576 + tid * 2;
    const int seg = blockIdx.z;

    const float* Kb = g_k + (size_t)(b * CH + h * DH) * LL;
    const float* Qb = g_q + (size_t)(b * CH + h * DH) * LL;

    u64 kp[8];
#pragma unroll
    for (int d = 0; d < 8; d++) {
        float2 kv = *(const float2*)&Kb[d * LL + k0];
        PACK2(kp[d], kv.x, kv.y);
    }

    __shared__ __align__(16) float2 sq[QSEG][8];
    const int q0 = seg * QSEG;
    for (int i = tid; i < QSEG * 8; i += 288) {
        const int d = i >> 8, qq = i & 255;
        float v = Qb[d * LL + q0 + qq];
        sq[qq][d] = make_float2(v, v);
    }
    __syncthreads();

    u64 Z = 0ull;   // packed {0,0}
#pragma unroll 4
    for (int qq = 0; qq < QSEG; qq++) {
        const ulonglong2* qr = (const ulonglong2*)sq[qq];
        ulonglong2 qa = qr[0], qb_ = qr[1], qc = qr[2], qd = qr[3];
        u64 u0, t0, l0;
        MUL2(u0, qa.x,  kp[0]); MUL2(t0, qc.x,  kp[4]);
        FMA2(u0, qa.y,  kp[1], u0); FMA2(t0, qc.y,  kp[5], t0);
        FMA2(u0, qb_.x, kp[2], u0); FMA2(t0, qd.x,  kp[6], t0);
        FMA2(u0, qb_.y, kp[3], u0); FMA2(t0, qd.y,  kp[7], t0);
        ADD2(l0, u0, t0);
        float a0, a1, e0, e1;
        UNPACK2(a0, a1, l0);
        EX2F(e0, a0); EX2F(e1, a1);
        u64 w0;
        PACK2(w0, e0, e1);
        ADD2(Z, Z, w0);
    }
    float z0, z1;
    UNPACK2(z0, z1, Z);
    *(float2*)&g_Z[seg][bh][k0] = make_float2(z0, z1);
}

// ---------------------------------------------------------------------------
// K3 (pass B): partial o over a k-segment.  Each thread owns 2 q columns.
// Z-sum + 1/Z + V-scaling fused into the SMEM fill (thread t<256 owns k=t).
// grid = (bh=16, qtile=4, seg=9) x 288 thr = 576 blocks.
// ---------------------------------------------------------------------------
__global__ __launch_bounds__(288) void k_passB()
{
    const int bh = blockIdx.x;
    const int b = bh >> 3, h = bh & 7;
    const int tid = threadIdx.x;
    const int q0 = blockIdx.y * 576 + tid * 2;
    const int seg = blockIdx.z;

    const float* Qb = g_q + (size_t)(b * CH + h * DH) * LL;
    const float* Kb = g_k + (size_t)(b * CH + h * DH) * LL;
    const float* Vb = g_v + (size_t)(b * CH + h * DH) * LL;

    u64 qp[8];
#pragma unroll
    for (int d = 0; d < 8; d++) {
        float2 qv = *(const float2*)&Qb[d * LL + q0];
        PACK2(qp[d], qv.x, qv.y);
    }

    __shared__ __align__(16) float2 sk[KSEG][8];
    __shared__ __align__(16) float2 sv[KSEG][8];
    const int kb = seg * KSEG;
    if (tid < KSEG) {
        const int kk = tid;
        float z = 0.f;
#pragma unroll
        for (int s = 0; s < SEGS; s++) z += g_Z[s][bh][kb + kk];
        const float inv = 1.0f / z;
#pragma unroll
        for (int d = 0; d < 8; d++) {
            float kval = Kb[d * LL + kb + kk];
            float vval = Vb[d * LL + kb + kk] * inv;
            sk[kk][d] = make_float2(kval, kval);
            sv[kk][d] = make_float2(vval, vval);
        }
    }
    __syncthreads();

    u64 o[8];
#pragma unroll
    for (int d = 0; d < 8; d++) o[d] = 0ull;

#pragma unroll 2
    for (int kk = 0; kk < KSEG; kk++) {
        const ulonglong2* kr = (const ulonglong2*)sk[kk];
        ulonglong2 ka = kr[0], kb_ = kr[1], kc = kr[2], kd = kr[3];
        u64 u0, t0, l0;
        MUL2(u0, qp[0], ka.x);  MUL2(t0, qp[4], kc.x);
        FMA2(u0, qp[1], ka.y,  u0); FMA2(t0, qp[5], kc.y,  t0);
        FMA2(u0, qp[2], kb_.x, u0); FMA2(t0, qp[6], kd.x,  t0);
        FMA2(u0, qp[3], kb_.y, u0); FMA2(t0, qp[7], kd.y,  t0);
        ADD2(l0, u0, t0);
        float a0, a1, e0, e1;
        UNPACK2(a0, a1, l0);
        EX2F(e0, a0); EX2F(e1, a1);
        u64 w0;
        PACK2(w0, e0, e1);
        const ulonglong2* vr = (const ulonglong2*)sv[kk];
        ulonglong2 va = vr[0], vb_ = vr[1], vc = vr[2], vd = vr[3];
        FMA2(o[0], w0, va.x,  o[0]);
        FMA2(o[1], w0, va.y,  o[1]);
        FMA2(o[2], w0, vb_.x, o[2]);
        FMA2(o[3], w0, vb_.y, o[3]);
        FMA2(o[4], w0, vc.x,  o[4]);
        FMA2(o[5], w0, vc.y,  o[5]);
        FMA2(o[6], w0, vd.x,  o[6]);
        FMA2(o[7], w0, vd.y,  o[7]);
    }

    float* Ob = g_op[seg] + (size_t)(b * CH + h * DH) * LL;
#pragma unroll
    for (int d = 0; d < 8; d++) {
        float x0, x1;
        UNPACK2(x0, x1, o[d]);
        *(float2*)&Ob[d * LL + q0] = make_float2(x0, x1);
    }
}

// ---------------------------------------------------------------------------
// K4: reduce o partials across the 9 k-segments (streaming, coalesced).
// ---------------------------------------------------------------------------
__global__ __launch_bounds__(256) void k_reduce()
{
    const int i = blockIdx.x * 256 + threadIdx.x;  // over BCHL/4 = 73728
    float4 a = ((const float4*)g_op[0])[i];
#pragma unroll
    for (int s = 1; s < SEGS; s++) {
        float4 t = ((const float4*)g_op[s])[i];
        a.x += t.x; a.y += t.y; a.z += t.z; a.w += t.w;
    }
    ((float4*)g_o)[i] = a;
}

// ---------------------------------------------------------------------------
// K5: output 1x1 conv.  grid = 288 blocks x 256 thr.
// ---------------------------------------------------------------------------
__global__ __launch_bounds__(256) void k_oconv(
    const float* __restrict__ Wo, const float* __restrict__ bo,
    float* __restrict__ out)
{
    __shared__ __align__(16) float sW[64*64];
    __shared__ float sb[64];
    const int tid = threadIdx.x;
    for (int i = tid; i < 4096; i += 256) sW[i] = Wo[i];
    if (tid < 64) sb[tid] = bo[tid];
    __syncthreads();

    const int col = blockIdx.x * 16 + (tid & 15);
    const int og  = tid >> 4;
    const int b   = col / LL;
    const int l   = col - b * LL;

    const float* xp = g_o + (size_t)b * CH * LL + l;
    float xr[64];
#pragma unroll
    for (int c = 0; c < 64; c++) xr[c] = xp[c * LL];

#pragma unroll
    for (int j = 0; j < 4; j++) {
        const int o = og * 4 + j;
        const float4* wr = (const float4*)&sW[o * 64];
        float a0 = 0.f, a1 = 0.f, a2 = 0.f, a3 = 0.f;
#pragma unroll
        for (int c4 = 0; c4 < 16; c4++) {
            float4 w = wr[c4];
            a0 = fmaf(w.x, xr[c4*4+0], a0);
            a1 = fmaf(w.y, xr[c4*4+1], a1);
            a2 = fmaf(w.z, xr[c4*4+2], a2);
            a3 = fmaf(w.w, xr[c4*4+3], a3);
        }
        out[((size_t)b * CH + o) * LL + l] = (a0 + a1) + (a2 + a3) + sb[o];
    }
}

// ---------------------------------------------------------------------------
extern "C" void kernel_launch(void* const* d_in, const int* in_sizes, int n_in,
                              void* d_out, int out_size)
{
    const float* x  = (const float*)d_in[0];
    const float* Wq = (const float*)d_in[1];
    const float* bq = (const float*)d_in[2];
    const float* Wk = (const float*)d_in[3];
    const float* bk = (const float*)d_in[4];
    const float* Wv = (const float*)d_in[5];
    const float* bv = (const float*)d_in[6];
    const float* Wo = (const float*)d_in[7];
    const float* bo = (const float*)d_in[8];

    float* out   = (float*)d_out;           // first output: conv result
    float* q_out = (float*)d_out + BCHL;    // second output: scaled q

    k_qkv<<<288, 256>>>(x, Wq, bq, Wk, bk, Wv, bv, q_out);
    k_passA<<<dim3(16, 4, SEGS), 288>>>();
    k_passB<<<dim3(16, 4, SEGS), 288>>>();
    k_reduce<<<288, 256>>>();
    k_oconv<<<288, 256>>>(Wo, bo, out);
}

// round 7
// speedup vs baseline: 1.2101x; 1.2101x over previous
#include <cuda_runtime.h>

// Problem constants (fixed by the reference setup)
#define BB   2
#define CH   64
#define NH   8
#define DH   8
#define HW   48
#define LL   2304            // HW*HW
#define BCHL (BB*CH*LL)      // 294912
#define SEGS 9
#define QSEG 256             // LL/SEGS
#define KSEG 256

#define LOG2E 1.4426950408889634f

// Packed f32x2 helpers (sm_103a FFMA2 path)
#define FMA2(d,a,b,c) asm("fma.rn.f32x2 %0,%1,%2,%3;" : "=l"(d) : "l"(a), "l"(b), "l"(c))
#define MUL2(d,a,b)   asm("mul.rn.f32x2 %0,%1,%2;"    : "=l"(d) : "l"(a), "l"(b))
#define ADD2(d,a,b)   asm("add.rn.f32x2 %0,%1,%2;"    : "=l"(d) : "l"(a), "l"(b))
#define PACK2(d,x,y)  asm("mov.b64 %0,{%1,%2};"        : "=l"(d) : "f"(x), "f"(y))
#define UNPACK2(x,y,d) asm("mov.b64 {%0,%1},%2;"       : "=f"(x), "=f"(y) : "l"(d))
#define EX2F(r,x)     asm("ex2.approx.ftz.f32 %0,%1;"  : "=f"(r) : "f"(x))

typedef unsigned long long u64;

// Scratch (device globals — no allocation allowed)
__device__ float g_q [BCHL];          // q * d^-0.5 * log2(e)  (for EX2)
__device__ float g_k [BCHL];
__device__ float g_v [BCHL];
__device__ float g_o [BCHL];
__device__ float g_Z [SEGS][BB*NH][LL];
__device__ float g_op[SEGS][BCHL];

// ---------------------------------------------------------------------------
// K1: fused q/k/v 1x1 convs.  grid = 288 blocks x 256 thr.
// ---------------------------------------------------------------------------
__global__ __launch_bounds__(256) void k_qkv(
    const float* __restrict__ x,
    const float* __restrict__ Wq, const float* __restrict__ bq,
    const float* __restrict__ Wk, const float* __restrict__ bk,
    const float* __restrict__ Wv, const float* __restrict__ bv,
    float* __restrict__ q_out)
{
    __shared__ __align__(16) float sW[3][64*64];
    __shared__ float sb[3][64];
    const int tid = threadIdx.x;
    for (int i = tid; i < 4096; i += 256) {
        sW[0][i] = Wq[i]; sW[1][i] = Wk[i]; sW[2][i] = Wv[i];
    }
    if (tid < 64) { sb[0][tid] = bq[tid]; sb[1][tid] = bk[tid]; sb[2][tid] = bv[tid]; }
    __syncthreads();

    const int col = blockIdx.x * 16 + (tid & 15);     // 0..4607
    const int og  = tid >> 4;                          // 0..15
    const int b   = col / LL;
    const int l   = col - b * LL;

    const float* xp = x + (size_t)b * CH * LL + l;
    float xr[64];
#pragma unroll
    for (int c = 0; c < 64; c++) xr[c] = xp[c * LL];

    const float qscale = 0.35355339059327373f;  // 8^-0.5

#pragma unroll
    for (int m = 0; m < 3; m++) {
        float* dst = (m == 0) ? g_q : (m == 1) ? g_k : g_v;
#pragma unroll
        for (int j = 0; j < 4; j++) {
            const int o = og * 4 + j;
            const float4* wr = (const float4*)&sW[m][o * 64];
            float a0 = 0.f, a1 = 0.f, a2 = 0.f, a3 = 0.f;
#pragma unroll
            for (int c4 = 0; c4 < 16; c4++) {
                float4 w = wr[c4];
                a0 = fmaf(w.x, xr[c4*4+0], a0);
                a1 = fmaf(w.y, xr[c4*4+1], a1);
                a2 = fmaf(w.z, xr[c4*4+2], a2);
                a3 = fmaf(w.w, xr[c4*4+3], a3);
            }
            float r = (a0 + a1) + (a2 + a3) + sb[m][o];
            const size_t idx = ((size_t)b * CH + o) * LL + l;
            if (m == 0) {
                float rq = r * qscale;
                q_out[idx] = rq;                 // reference returns the SCALED q
                dst[idx]   = rq * LOG2E;         // internal: prescaled for EX2
            } else {
                dst[idx] = r;
            }
        }
    }
}

// ---------------------------------------------------------------------------
// K2 (pass A): partial Z over a q-segment.  4 k-cols/thread (2 packed pairs),
// depth-4 logit trees, 2-iteration batches with LDS issued up front.
// grid = (bh=16, ktile=2, seg=9) x 288 thr.
// ---------------------------------------------------------------------------
__global__ __launch_bounds__(288) void k_passA()
{
    const int bh = blockIdx.x;
    const int b = bh >> 3, h = bh & 7;
    const int tid = threadIdx.x;
    const int k0 = blockIdx.y * 1152 + tid * 4;
    const int seg = blockIdx.z;

    const float* Kb = g_k + (size_t)(b * CH + h * DH) * LL;
    const float* Qb = g_q + (size_t)(b * CH + h * DH) * LL;

    u64 kp0[8], kp1[8];
#pragma unroll
    for (int d = 0; d < 8; d++) {
        float4 kv = *(const float4*)&Kb[d * LL + k0];
        PACK2(kp0[d], kv.x, kv.y);
        PACK2(kp1[d], kv.z, kv.w);
    }

    __shared__ __align__(16) float2 sq[QSEG][8];
    const int q0 = seg * QSEG;
    for (int i = tid; i < QSEG * 8; i += 288) {
        const int d = i >> 8, qq = i & 255;
        float v = Qb[d * LL + q0 + qq];
        sq[qq][d] = make_float2(v, v);
    }
    __syncthreads();

    u64 Z0 = 0ull, Z1 = 0ull;   // packed {0,0}
#pragma unroll 1
    for (int qq = 0; qq < QSEG; qq += 2) {
        // batch both iterations' LDS up front
        const ulonglong2* qr0 = (const ulonglong2*)sq[qq];
        const ulonglong2* qr1 = (const ulonglong2*)sq[qq + 1];
        ulonglong2 qa = qr0[0], qb_ = qr0[1], qc = qr0[2], qd = qr0[3];
        ulonglong2 ra = qr1[0], rb_ = qr1[1], rc = qr1[2], rd = qr1[3];
        {
            u64 u0, t0, u1, t1, l0, l1;
            MUL2(u0, qa.x,  kp0[0]); MUL2(t0, qc.x,  kp0[4]);
            MUL2(u1, qa.x,  kp1[0]); MUL2(t1, qc.x,  kp1[4]);
            FMA2(u0, qa.y,  kp0[1], u0); FMA2(t0, qc.y,  kp0[5], t0);
            FMA2(u1, qa.y,  kp1[1], u1); FMA2(t1, qc.y,  kp1[5], t1);
            FMA2(u0, qb_.x, kp0[2], u0); FMA2(t0, qd.x,  kp0[6], t0);
            FMA2(u1, qb_.x, kp1[2], u1); FMA2(t1, qd.x,  kp1[6], t1);
            FMA2(u0, qb_.y, kp0[3], u0); FMA2(t0, qd.y,  kp0[7], t0);
            FMA2(u1, qb_.y, kp1[3], u1); FMA2(t1, qd.y,  kp1[7], t1);
            ADD2(l0, u0, t0);
            ADD2(l1, u1, t1);
            float a0, a1, b0, b1, e0, e1, e2, e3;
            UNPACK2(a0, a1, l0);
            UNPACK2(b0, b1, l1);
            EX2F(e0, a0); EX2F(e1, a1); EX2F(e2, b0); EX2F(e3, b1);
            u64 w0, w1;
            PACK2(w0, e0, e1);
            PACK2(w1, e2, e3);
            ADD2(Z0, Z0, w0);
            ADD2(Z1, Z1, w1);
        }
        {
            u64 u0, t0, u1, t1, l0, l1;
            MUL2(u0, ra.x,  kp0[0]); MUL2(t0, rc.x,  kp0[4]);
            MUL2(u1, ra.x,  kp1[0]); MUL2(t1, rc.x,  kp1[4]);
            FMA2(u0, ra.y,  kp0[1], u0); FMA2(t0, rc.y,  kp0[5], t0);
            FMA2(u1, ra.y,  kp1[1], u1); FMA2(t1, rc.y,  kp1[5], t1);
            FMA2(u0, rb_.x, kp0[2], u0); FMA2(t0, rd.x,  kp0[6], t0);
            FMA2(u1, rb_.x, kp1[2], u1); FMA2(t1, rd.x,  kp1[6], t1);
            FMA2(u0, rb_.y, kp0[3], u0); FMA2(t0, rd.y,  kp0[7], t0);
            FMA2(u1, rb_.y, kp1[3], u1); FMA2(t1, rd.y,  kp1[7], t1);
            ADD2(l0, u0, t0);
            ADD2(l1, u1, t1);
            float a0, a1, b0, b1, e0, e1, e2, e3;
            UNPACK2(a0, a1, l0);
            UNPACK2(b0, b1, l1);
            EX2F(e0, a0); EX2F(e1, a1); EX2F(e2, b0); EX2F(e3, b1);
            u64 w0, w1;
            PACK2(w0, e0, e1);
            PACK2(w1, e2, e3);
            ADD2(Z0, Z0, w0);
            ADD2(Z1, Z1, w1);
        }
    }
    float z0, z1, z2, z3;
    UNPACK2(z0, z1, Z0);
    UNPACK2(z2, z3, Z1);
    *(float4*)&g_Z[seg][bh][k0] = make_float4(z0, z1, z2, z3);
}

// ---------------------------------------------------------------------------
// K3 (pass B): partial o over a k-segment.  4 q-cols/thread, fused zsum into
// the SMEM fill, depth-4 trees, 2-iteration LDS batching.
// grid = (bh=16, qtile=2, seg=9) x 288 thr.
// ---------------------------------------------------------------------------
__global__ __launch_bounds__(288) void k_passB()
{
    const int bh = blockIdx.x;
    const int b = bh >> 3, h = bh & 7;
    const int tid = threadIdx.x;
    const int q0 = blockIdx.y * 1152 + tid * 4;
    const int seg = blockIdx.z;

    const float* Qb = g_q + (size_t)(b * CH + h * DH) * LL;
    const float* Kb = g_k + (size_t)(b * CH + h * DH) * LL;
    const float* Vb = g_v + (size_t)(b * CH + h * DH) * LL;

    u64 qp0[8], qp1[8];
#pragma unroll
    for (int d = 0; d < 8; d++) {
        float4 qv = *(const float4*)&Qb[d * LL + q0];
        PACK2(qp0[d], qv.x, qv.y);
        PACK2(qp1[d], qv.z, qv.w);
    }

    __shared__ __align__(16) float2 sk[KSEG][8];
    __shared__ __align__(16) float2 sv[KSEG][8];
    const int kb = seg * KSEG;
    if (tid < KSEG) {
        const int kk = tid;
        float z = 0.f;
#pragma unroll
        for (int s = 0; s < SEGS; s++) z += g_Z[s][bh][kb + kk];
        const float inv = 1.0f / z;
#pragma unroll
        for (int d = 0; d < 8; d++) {
            float kval = Kb[d * LL + kb + kk];
            float vval = Vb[d * LL + kb + kk] * inv;
            sk[kk][d] = make_float2(kval, kval);
            sv[kk][d] = make_float2(vval, vval);
        }
    }
    __syncthreads();

    u64 o0[8], o1[8];
#pragma unroll
    for (int d = 0; d < 8; d++) { o0[d] = 0ull; o1[d] = 0ull; }

#pragma unroll 1
    for (int kk = 0; kk < KSEG; kk += 2) {
        // batch both iterations' K LDS up front (V loaded after exp is ready)
        const ulonglong2* kr0 = (const ulonglong2*)sk[kk];
        const ulonglong2* kr1 = (const ulonglong2*)sk[kk + 1];
        ulonglong2 ka = kr0[0], kb_ = kr0[1], kc = kr0[2], kd = kr0[3];
        ulonglong2 ma = kr1[0], mb_ = kr1[1], mc = kr1[2], md = kr1[3];
        const ulonglong2* vr0 = (const ulonglong2*)sv[kk];
        const ulonglong2* vr1 = (const ulonglong2*)sv[kk + 1];
        {
            u64 u0, t0, u1, t1, l0, l1;
            MUL2(u0, qp0[0], ka.x);  MUL2(t0, qp0[4], kc.x);
            MUL2(u1, qp1[0], ka.x);  MUL2(t1, qp1[4], kc.x);
            FMA2(u0, qp0[1], ka.y,  u0); FMA2(t0, qp0[5], kc.y,  t0);
            FMA2(u1, qp1[1], ka.y,  u1); FMA2(t1, qp1[5], kc.y,  t1);
            FMA2(u0, qp0[2], kb_.x, u0); FMA2(t0, qp0[6], kd.x,  t0);
            FMA2(u1, qp1[2], kb_.x, u1); FMA2(t1, qp1[6], kd.x,  t1);
            FMA2(u0, qp0[3], kb_.y, u0); FMA2(t0, qp0[7], kd.y,  t0);
            FMA2(u1, qp1[3], kb_.y, u1); FMA2(t1, qp1[7], kd.y,  t1);
            ADD2(l0, u0, t0);
            ADD2(l1, u1, t1);
            float a0, a1, b0, b1, e0, e1, e2, e3;
            UNPACK2(a0, a1, l0);
            UNPACK2(b0, b1, l1);
            EX2F(e0, a0); EX2F(e1, a1); EX2F(e2, b0); EX2F(e3, b1);
            u64 w0, w1;
            PACK2(w0, e0, e1);
            PACK2(w1, e2, e3);
            ulonglong2 va = vr0[0], vb_ = vr0[1], vc = vr0[2], vd = vr0[3];
            FMA2(o0[0], w0, va.x,  o0[0]); FMA2(o1[0], w1, va.x,  o1[0]);
            FMA2(o0[1], w0, va.y,  o0[1]); FMA2(o1[1], w1, va.y,  o1[1]);
            FMA2(o0[2], w0, vb_.x, o0[2]); FMA2(o1[2], w1, vb_.x, o1[2]);
            FMA2(o0[3], w0, vb_.y, o0[3]); FMA2(o1[3], w1, vb_.y, o1[3]);
            FMA2(o0[4], w0, vc.x,  o0[4]); FMA2(o1[4], w1, vc.x,  o1[4]);
            FMA2(o0[5], w0, vc.y,  o0[5]); FMA2(o1[5], w1, vc.y,  o1[5]);
            FMA2(o0[6], w0, vd.x,  o0[6]); FMA2(o1[6], w1, vd.x,  o1[6]);
            FMA2(o0[7], w0, vd.y,  o0[7]); FMA2(o1[7], w1, vd.y,  o1[7]);
        }
        {
            u64 u0, t0, u1, t1, l0, l1;
            MUL2(u0, qp0[0], ma.x);  MUL2(t0, qp0[4], mc.x);
            MUL2(u1, qp1[0], ma.x);  MUL2(t1, qp1[4], mc.x);
            FMA2(u0, qp0[1], ma.y,  u0); FMA2(t0, qp0[5], mc.y,  t0);
            FMA2(u1, qp1[1], ma.y,  u1); FMA2(t1, qp1[5], mc.y,  t1);
            FMA2(u0, qp0[2], mb_.x, u0); FMA2(t0, qp0[6], md.x,  t0);
            FMA2(u1, qp1[2], mb_.x, u1); FMA2(t1, qp1[6], md.x,  t1);
            FMA2(u0, qp0[3], mb_.y, u0); FMA2(t0, qp0[7], md.y,  t0);
            FMA2(u1, qp1[3], mb_.y, u1); FMA2(t1, qp1[7], md.y,  t1);
            ADD2(l0, u0, t0);
            ADD2(l1, u1, t1);
            float a0, a1, b0, b1, e0, e1, e2, e3;
            UNPACK2(a0, a1, l0);
            UNPACK2(b0, b1, l1);
            EX2F(e0, a0); EX2F(e1, a1); EX2F(e2, b0); EX2F(e3, b1);
            u64 w0, w1;
            PACK2(w0, e0, e1);
            PACK2(w1, e2, e3);
            ulonglong2 va = vr1[0], vb_ = vr1[1], vc = vr1[2], vd = vr1[3];
            FMA2(o0[0], w0, va.x,  o0[0]); FMA2(o1[0], w1, va.x,  o1[0]);
            FMA2(o0[1], w0, va.y,  o0[1]); FMA2(o1[1], w1, va.y,  o1[1]);
            FMA2(o0[2], w0, vb_.x, o0[2]); FMA2(o1[2], w1, vb_.x, o1[2]);
            FMA2(o0[3], w0, vb_.y, o0[3]); FMA2(o1[3], w1, vb_.y, o1[3]);
            FMA2(o0[4], w0, vc.x,  o0[4]); FMA2(o1[4], w1, vc.x,  o1[4]);
            FMA2(o0[5], w0, vc.y,  o0[5]); FMA2(o1[5], w1, vc.y,  o1[5]);
            FMA2(o0[6], w0, vd.x,  o0[6]); FMA2(o1[6], w1, vd.x,  o1[6]);
            FMA2(o0[7], w0, vd.y,  o0[7]); FMA2(o1[7], w1, vd.y,  o1[7]);
        }
    }

    float* Ob = g_op[seg] + (size_t)(b * CH + h * DH) * LL;
#pragma unroll
    for (int d = 0; d < 8; d++) {
        float x0, x1, x2, x3;
        UNPACK2(x0, x1, o0[d]);
        UNPACK2(x2, x3, o1[d]);
        *(float4*)&Ob[d * LL + q0] = make_float4(x0, x1, x2, x3);
    }
}

// ---------------------------------------------------------------------------
// K4: reduce o partials across the 9 k-segments (streaming, coalesced).
// ---------------------------------------------------------------------------
__global__ __launch_bounds__(256) void k_reduce()
{
    const int i = blockIdx.x * 256 + threadIdx.x;  // over BCHL/4 = 73728
    float4 a = ((const float4*)g_op[0])[i];
#pragma unroll
    for (int s = 1; s < SEGS; s++) {
        float4 t = ((const float4*)g_op[s])[i];
        a.x += t.x; a.y += t.y; a.z += t.z; a.w += t.w;
    }
    ((float4*)g_o)[i] = a;
}

// ---------------------------------------------------------------------------
// K5: output 1x1 conv.  grid = 288 blocks x 256 thr.
// ---------------------------------------------------------------------------
__global__ __launch_bounds__(256) void k_oconv(
    const float* __restrict__ Wo, const float* __restrict__ bo,
    float* __restrict__ out)
{
    __shared__ __align__(16) float sW[64*64];
    __shared__ float sb[64];
    const int tid = threadIdx.x;
    for (int i = tid; i < 4096; i += 256) sW[i] = Wo[i];
    if (tid < 64) sb[tid] = bo[tid];
    __syncthreads();

    const int col = blockIdx.x * 16 + (tid & 15);
    const int og  = tid >> 4;
    const int b   = col / LL;
    const int l   = col - b * LL;

    const float* xp = g_o + (size_t)b * CH * LL + l;
    float xr[64];
#pragma unroll
    for (int c = 0; c < 64; c++) xr[c] = xp[c * LL];

#pragma unroll
    for (int j = 0; j < 4; j++) {
        const int o = og * 4 + j;
        const float4* wr = (const float4*)&sW[o * 64];
        float a0 = 0.f, a1 = 0.f, a2 = 0.f, a3 = 0.f;
#pragma unroll
        for (int c4 = 0; c4 < 16; c4++) {
            float4 w = wr[c4];
            a0 = fmaf(w.x, xr[c4*4+0], a0);
            a1 = fmaf(w.y, xr[c4*4+1], a1);
            a2 = fmaf(w.z, xr[c4*4+2], a2);
            a3 = fmaf(w.w, xr[c4*4+3], a3);
        }
        out[((size_t)b * CH + o) * LL + l] = (a0 + a1) + (a2 + a3) + sb[o];
    }
}

// ---------------------------------------------------------------------------
extern "C" void kernel_launch(void* const* d_in, const int* in_sizes, int n_in,
                              void* d_out, int out_size)
{
    const float* x  = (const float*)d_in[0];
    const float* Wq = (const float*)d_in[1];
    const float* bq = (const float*)d_in[2];
    const float* Wk = (const float*)d_in[3];
    const float* bk = (const float*)d_in[4];
    const float* Wv = (const float*)d_in[5];
    const float* bv = (const float*)d_in[6];
    const float* Wo = (const float*)d_in[7];
    const float* bo = (const float*)d_in[8];

    float* out   = (float*)d_out;           // first output: conv result
    float* q_out = (float*)d_out + BCHL;    // second output: scaled q

    k_qkv<<<288, 256>>>(x, Wq, bq, Wk, bk, Wv, bv, q_out);
    k_passA<<<dim3(16, 2, SEGS), 288>>>();
    k_passB<<<dim3(16, 2, SEGS), 288>>>();
    k_reduce<<<288, 256>>>();
    k_oconv<<<288, 256>>>(Wo, bo, out);
}